// round 8
// baseline (speedup 1.0000x reference)
#include <cuda_runtime.h>
#include <cuda_bf16.h>
#include <cstdint>

#define DIMSZ 2048
#define NHEADS 16
#define HDIM 128
#define BSZ 2
#define LSEQ 2048
#define MROWS (BSZ * LSEQ)   // 4096
#define KDIM 2048
#define SCALE_F 0.08838834764831845f

// ---------------------------------------------------------------------------
// Scratch (__device__ globals; no allocation allowed)
// ---------------------------------------------------------------------------
__device__ __nv_bfloat16 g_xh[(size_t)MROWS * DIMSZ];
__device__ __nv_bfloat16 g_xl[(size_t)MROWS * DIMSZ];
__device__ __nv_bfloat16 g_ch[(size_t)MROWS * DIMSZ];
__device__ __nv_bfloat16 g_cl[(size_t)MROWS * DIMSZ];
__device__ __nv_bfloat16 g_wqh[(size_t)3 * DIMSZ * DIMSZ];  // W_qkv^T [6144][2048]
__device__ __nv_bfloat16 g_wql[(size_t)3 * DIMSZ * DIMSZ];
__device__ __nv_bfloat16 g_wph[(size_t)DIMSZ * DIMSZ];      // W_proj^T [2048][2048]
__device__ __nv_bfloat16 g_wpl[(size_t)DIMSZ * DIMSZ];
__device__ __nv_bfloat16 g_qh[(size_t)MROWS * DIMSZ];
__device__ __nv_bfloat16 g_ql[(size_t)MROWS * DIMSZ];
__device__ __nv_bfloat16 g_kvh[(size_t)MROWS * 2 * DIMSZ];
__device__ __nv_bfloat16 g_kvl[(size_t)MROWS * 2 * DIMSZ];
__device__ __nv_bfloat16 g_ath[(size_t)MROWS * DIMSZ];
__device__ __nv_bfloat16 g_atl[(size_t)MROWS * DIMSZ];

// ---------------------------------------------------------------------------
// PTX helpers (baseline ISA: ldmatrix / mma.sync / cp.async)
// ---------------------------------------------------------------------------
__device__ __forceinline__ uint32_t smem_to_u32(const void* p) {
    uint32_t a;
    asm("{ .reg .u64 t; cvta.to.shared.u64 t, %1; cvt.u32.u64 %0, t; }" : "=r"(a) : "l"(p));
    return a;
}

#define CP_ASYNC16(dst, src) \
    asm volatile("cp.async.cg.shared.global [%0], [%1], 16;" :: "r"(dst), "l"(src) : "memory")
#define CP_COMMIT() asm volatile("cp.async.commit_group;" ::: "memory")
#define CP_WAIT(n)  asm volatile("cp.async.wait_group %0;" :: "n"(n) : "memory")

#define LDSM_X4(r0, r1, r2, r3, addr) \
    asm volatile("ldmatrix.sync.aligned.m8n8.x4.shared.b16 {%0,%1,%2,%3}, [%4];" \
                 : "=r"(r0), "=r"(r1), "=r"(r2), "=r"(r3) : "r"(addr))
#define LDSM_X4_T(r0, r1, r2, r3, addr) \
    asm volatile("ldmatrix.sync.aligned.m8n8.x4.trans.shared.b16 {%0,%1,%2,%3}, [%4];" \
                 : "=r"(r0), "=r"(r1), "=r"(r2), "=r"(r3) : "r"(addr))

#define MMA16816(d, a, b0, b1) \
    asm volatile("mma.sync.aligned.m16n8k16.row.col.f32.bf16.bf16.f32 " \
                 "{%0,%1,%2,%3}, {%4,%5,%6,%7}, {%8,%9}, {%0,%1,%2,%3};" \
                 : "+f"((d)[0]), "+f"((d)[1]), "+f"((d)[2]), "+f"((d)[3]) \
                 : "r"((a)[0]), "r"((a)[1]), "r"((a)[2]), "r"((a)[3]), \
                   "r"(b0), "r"(b1))

__device__ __forceinline__ uint32_t packbf(float lo, float hi) {
    uint32_t r;
    asm("cvt.rn.bf16x2.f32 %0, %1, %2;" : "=r"(r) : "f"(hi), "f"(lo));
    return r;
}
__device__ __forceinline__ float bflo_f(uint32_t u) { return __uint_as_float(u << 16); }
__device__ __forceinline__ float bfhi_f(uint32_t u) { return __uint_as_float(u & 0xffff0000u); }

// ---------------------------------------------------------------------------
// Conversion kernels
// ---------------------------------------------------------------------------
__global__ __launch_bounds__(256)
void split_fp32(const float* __restrict__ in, __nv_bfloat16* __restrict__ h,
                __nv_bfloat16* __restrict__ l, int n4)
{
    int i = blockIdx.x * 256 + threadIdx.x;
    if (i >= n4) return;
    float4 v = ((const float4*)in)[i];
    uint32_t h01 = packbf(v.x, v.y), h23 = packbf(v.z, v.w);
    uint32_t l01 = packbf(v.x - bflo_f(h01), v.y - bfhi_f(h01));
    uint32_t l23 = packbf(v.z - bflo_f(h23), v.w - bfhi_f(h23));
    ((uint32_t*)h)[2 * i] = h01; ((uint32_t*)h)[2 * i + 1] = h23;
    ((uint32_t*)l)[2 * i] = l01; ((uint32_t*)l)[2 * i + 1] = l23;
}

__global__ __launch_bounds__(256)
void transpose_split(const float* __restrict__ in, __nv_bfloat16* __restrict__ h,
                     __nv_bfloat16* __restrict__ l, int R, int C)
{
    __shared__ float tile[32][33];
    int c0 = blockIdx.x * 32, r0 = blockIdx.y * 32;
    int tx = threadIdx.x & 31, ty = threadIdx.x >> 5;
#pragma unroll
    for (int i = 0; i < 4; i++)
        tile[ty + 8 * i][tx] = in[(size_t)(r0 + ty + 8 * i) * C + c0 + tx];
    __syncthreads();
#pragma unroll
    for (int i = 0; i < 4; i++) {
        float v = tile[tx][ty + 8 * i];
        __nv_bfloat16 hv = __float2bfloat16(v);
        __nv_bfloat16 lv = __float2bfloat16(v - __bfloat162float(hv));
        size_t o = (size_t)(c0 + ty + 8 * i) * R + r0 + tx;
        h[o] = hv; l[o] = lv;
    }
}

// ---------------------------------------------------------------------------
// Persistent mma.sync split-bf16 GEMM: C = A @ B^T + bias (3 passes)
// CTA 128x128x32, 8 warps (warp tile 32m x 64n), double-buffered cp.async,
// 2 CTAs/SM; grid = 2*numSM, each CTA grid-strides over output tiles.
// Tile order: supertiles of 8 n-tiles, m-major inside (L2 reuse of B).
// ---------------------------------------------------------------------------
#define GBM 128
#define GBN 128
#define GBK 32
#define NCH (KDIM / GBK)         // 64
#define ROWB 80
#define TILE_B (128 * ROWB)      // 10240
#define STAGE_B (4 * TILE_B)     // 40960 : [Ah][Al][Bh][Bl]
#define GEMM_SMEM (2 * STAGE_B)  // 81920
#define NGRP 8

__global__ __launch_bounds__(256, 2)
void gemm_mma(const __nv_bfloat16* __restrict__ Ah0, const __nv_bfloat16* __restrict__ Al0,
              const __nv_bfloat16* __restrict__ Ah1, const __nv_bfloat16* __restrict__ Al1,
              const __nv_bfloat16* __restrict__ Bh, const __nv_bfloat16* __restrict__ Bl,
              const float* __restrict__ bias,
              float* __restrict__ Cf0, int ldc0, float* __restrict__ Cf1, int ldc1,
              __nv_bfloat16* __restrict__ Ch0, __nv_bfloat16* __restrict__ Cl0,
              __nv_bfloat16* __restrict__ Ch1, __nv_bfloat16* __restrict__ Cl1,
              int nsplit, int outmode, int tmcnt, int tncnt)
{
    extern __shared__ char sm[];
    const uint32_t sbase = smem_to_u32(sm);
    const int tid  = threadIdx.x;
    const int lane = tid & 31;
    const int wid  = tid >> 5;
    const int wm   = (wid & 3) * 32;   // warp m offset
    const int wn   = (wid >> 2) * 64;  // warp n offset

    uint32_t aoff[2][2];
#pragma unroll
    for (int mf = 0; mf < 2; mf++)
#pragma unroll
        for (int ks = 0; ks < 2; ks++)
            aoff[mf][ks] = (uint32_t)((wm + mf * 16 + (lane & 15)) * ROWB
                                      + (ks * 16 + 8 * (lane >> 4)) * 2);
    uint32_t boff[4][2];
#pragma unroll
    for (int jj = 0; jj < 4; jj++)
#pragma unroll
        for (int ks = 0; ks < 2; ks++)
            boff[jj][ks] = (uint32_t)((wn + jj * 16 + (lane & 7) + 8 * (lane >> 4)) * ROWB
                                      + (ks * 16 + 8 * ((lane >> 3) & 1)) * 2);

    const int ntiles = tmcnt * tncnt;

    for (int t = blockIdx.x; t < ntiles; t += gridDim.x) {
        // supertile mapping: groups of NGRP n-tiles, m-major inside
        const int grp_w   = (tncnt >= NGRP) ? NGRP : tncnt;
        const int per_grp = tmcnt * grp_w;
        const int ng      = t / per_grp;
        const int rem     = t % per_grp;
        const int gw      = ((ng + 1) * grp_w <= tncnt) ? grp_w : (tncnt - ng * grp_w);
        const int tm      = rem / gw;
        const int tn      = ng * grp_w + rem % gw;
        const int m0 = tm * GBM;
        const int n0 = tn * GBN;

        const __nv_bfloat16* Ah = (n0 < nsplit) ? Ah0 : Ah1;
        const __nv_bfloat16* Al = (n0 < nsplit) ? Al0 : Al1;

        float acc[2][8][4];
#pragma unroll
        for (int i = 0; i < 2; i++)
#pragma unroll
            for (int j = 0; j < 8; j++)
#pragma unroll
                for (int r = 0; r < 4; r++) acc[i][j][r] = 0.f;

        auto load_chunk = [&](int ic, int s) {
            const int k0 = ic * GBK;
#pragma unroll
            for (int it = 0; it < 8; it++) {
                const int tile   = it >> 1;             // 0:Ah 1:Al 2:Bh 3:Bl
                const int within = (it & 1) * 256 + tid;
                const int row    = within >> 2;
                const int seg    = within & 3;
                const __nv_bfloat16* src;
                if (tile == 0)      src = Ah + (size_t)(m0 + row) * KDIM + k0 + seg * 8;
                else if (tile == 1) src = Al + (size_t)(m0 + row) * KDIM + k0 + seg * 8;
                else if (tile == 2) src = Bh + (size_t)(n0 + row) * KDIM + k0 + seg * 8;
                else                src = Bl + (size_t)(n0 + row) * KDIM + k0 + seg * 8;
                uint32_t dst = sbase + s * STAGE_B + tile * TILE_B + row * ROWB + seg * 16;
                CP_ASYNC16(dst, src);
            }
            CP_COMMIT();
        };

        load_chunk(0, 0);

        for (int ic = 0; ic < NCH; ic++) {
            const int s = ic & 1;
            if (ic + 1 < NCH) { load_chunk(ic + 1, s ^ 1); CP_WAIT(1); }
            else              { CP_WAIT(0); }
            __syncthreads();

            const uint32_t stage = sbase + s * STAGE_B;
#pragma unroll
            for (int pass = 0; pass < 3; pass++) {
                const uint32_t Abase = stage + ((pass == 2) ? TILE_B : 0);
                const uint32_t Bbase = stage + 2 * TILE_B + ((pass == 1) ? TILE_B : 0);
#pragma unroll
                for (int ks = 0; ks < 2; ks++) {
                    uint32_t a[2][4];
                    LDSM_X4(a[0][0], a[0][1], a[0][2], a[0][3], Abase + aoff[0][ks]);
                    LDSM_X4(a[1][0], a[1][1], a[1][2], a[1][3], Abase + aoff[1][ks]);
#pragma unroll
                    for (int jj = 0; jj < 4; jj++) {
                        uint32_t b0, b1, b2, b3;
                        LDSM_X4(b0, b1, b2, b3, Bbase + boff[jj][ks]);
                        MMA16816(acc[0][jj * 2],     a[0], b0, b1);
                        MMA16816(acc[1][jj * 2],     a[1], b0, b1);
                        MMA16816(acc[0][jj * 2 + 1], a[0], b2, b3);
                        MMA16816(acc[1][jj * 2 + 1], a[1], b2, b3);
                    }
                }
            }
            __syncthreads();
        }

        // Epilogue
        int ld, nc0;
        float* Cf; __nv_bfloat16 *Ch, *Cl;
        if (n0 < nsplit) { Cf = Cf0; Ch = Ch0; Cl = Cl0; ld = ldc0; nc0 = n0; }
        else             { Cf = Cf1; Ch = Ch1; Cl = Cl1; ld = ldc1; nc0 = n0 - nsplit; }

#pragma unroll
        for (int mf = 0; mf < 2; mf++) {
#pragma unroll
            for (int nf = 0; nf < 8; nf++) {
                const int nl = wn + nf * 8 + 2 * (lane & 3);
                const float bx = bias[n0 + nl];
                const float by = bias[n0 + nl + 1];
                const int m_up = m0 + wm + mf * 16 + (lane >> 2);
#pragma unroll
                for (int half = 0; half < 2; half++) {
                    const int m = m_up + 8 * half;
                    float v0 = acc[mf][nf][2 * half]     + bx;
                    float v1 = acc[mf][nf][2 * half + 1] + by;
                    if (outmode == 0) {
                        float2 v; v.x = v0; v.y = v1;
                        *(float2*)(Cf + (size_t)m * ld + nc0 + nl) = v;
                    } else {
                        uint32_t hi = packbf(v0, v1);
                        uint32_t lo = packbf(v0 - bflo_f(hi), v1 - bfhi_f(hi));
                        *(uint32_t*)(Ch + (size_t)m * ld + nc0 + nl) = hi;
                        *(uint32_t*)(Cl + (size_t)m * ld + nc0 + nl) = lo;
                    }
                }
            }
        }
    }
}

// ---------------------------------------------------------------------------
// Tensor-core flash attention (split-bf16, 3-pass) — unchanged from R7
// ---------------------------------------------------------------------------
#define ASTR 272
#define Q_TILE (128 * ASTR)
#define KV_TILE (64 * ASTR)
#define KV_STAGE (4 * KV_TILE)
#define ATT_SMEM (2 * Q_TILE + 2 * KV_STAGE)

__global__ __launch_bounds__(256, 1)
void attn_mma(const __nv_bfloat16* __restrict__ Qh, const __nv_bfloat16* __restrict__ Ql,
              const __nv_bfloat16* __restrict__ KVh, const __nv_bfloat16* __restrict__ KVl,
              __nv_bfloat16* __restrict__ Oh, __nv_bfloat16* __restrict__ Ol)
{
    extern __shared__ char sm[];
    const uint32_t sQh = smem_to_u32(sm);
    const uint32_t sQl = sQh + Q_TILE;
    const uint32_t sKV = sQl + Q_TILE;

    const int tid  = threadIdx.x;
    const int lane = tid & 31;
    const int wid  = tid >> 5;
    const int wm   = wid * 16;

    const int qt = blockIdx.x, h = blockIdx.y, b = blockIdx.z;
    const int qrow0 = b * LSEQ + qt * 128;
    const int hcol  = h * HDIM;

#pragma unroll
    for (int i = 0; i < 8; i++) {
        int idx = i * 256 + tid;
        int row = idx >> 4, seg = idx & 15;
        size_t g = (size_t)(qrow0 + row) * DIMSZ + hcol + seg * 8;
        uint32_t d = row * ASTR + seg * 16;
        CP_ASYNC16(sQh + d, Qh + g);
        CP_ASYNC16(sQl + d, Ql + g);
    }
    CP_COMMIT();

    auto load_kv = [&](int jt, int s) {
        const uint32_t base = sKV + s * KV_STAGE;
        const int krow0 = b * LSEQ + jt * 64;
#pragma unroll
        for (int i = 0; i < 4; i++) {
            int idx = i * 256 + tid;
            int row = idx >> 4, seg = idx & 15;
            size_t roff = (size_t)(krow0 + row) * (2 * DIMSZ);
            uint32_t d = row * ASTR + seg * 16;
            CP_ASYNC16(base + d,               KVh + roff + hcol + seg * 8);
            CP_ASYNC16(base + KV_TILE + d,     KVl + roff + hcol + seg * 8);
            CP_ASYNC16(base + 2 * KV_TILE + d, KVh + roff + DIMSZ + hcol + seg * 8);
            CP_ASYNC16(base + 3 * KV_TILE + d, KVl + roff + DIMSZ + hcol + seg * 8);
        }
        CP_COMMIT();
    };
    load_kv(0, 0);

    const uint32_t ab = (uint32_t)((wm + (lane & 15)) * ASTR + (lane >> 4) * 16);
    const uint32_t kb = (uint32_t)(((lane & 7) + 8 * (lane >> 4)) * ASTR
                                   + ((lane >> 3) & 1) * 16);
    const uint32_t vb = (uint32_t)(((lane & 7) + 8 * ((lane >> 3) & 1)) * ASTR
                                   + (lane >> 4) * 16);

    float oacc[16][4];
#pragma unroll
    for (int f = 0; f < 16; f++)
#pragma unroll
        for (int e = 0; e < 4; e++) oacc[f][e] = 0.f;
    float m_prev[2] = {-3.0e38f, -3.0e38f};
    float l_acc[2]  = {0.f, 0.f};

    for (int jt = 0; jt < LSEQ / 64; jt++) {
        const int s = jt & 1;
        const bool has_next = (jt + 1 < LSEQ / 64);
        if (has_next) load_kv(jt + 1, s ^ 1);
        if (has_next) { CP_WAIT(1); } else { CP_WAIT(0); }
        __syncthreads();

        const uint32_t sK  = sKV + s * KV_STAGE;
        const uint32_t sKl = sK + KV_TILE;
        const uint32_t sV  = sK + 2 * KV_TILE;
        const uint32_t sVl = sK + 3 * KV_TILE;

        float sacc[8][4];
#pragma unroll
        for (int f = 0; f < 8; f++)
#pragma unroll
            for (int e = 0; e < 4; e++) sacc[f][e] = 0.f;

#pragma unroll
        for (int ks = 0; ks < 8; ks++) {
            uint32_t ah[4], al[4];
            LDSM_X4(ah[0], ah[1], ah[2], ah[3], sQh + ab + ks * 32);
            LDSM_X4(al[0], al[1], al[2], al[3], sQl + ab + ks * 32);
#pragma unroll
            for (int jj = 0; jj < 4; jj++) {
                uint32_t h0, h1, h2, h3, l0, l1, l2, l3;
                LDSM_X4(h0, h1, h2, h3, sK  + kb + jj * (16 * ASTR) + ks * 32);
                LDSM_X4(l0, l1, l2, l3, sKl + kb + jj * (16 * ASTR) + ks * 32);
                MMA16816(sacc[2 * jj],     ah, h0, h1);
                MMA16816(sacc[2 * jj + 1], ah, h2, h3);
                MMA16816(sacc[2 * jj],     ah, l0, l1);
                MMA16816(sacc[2 * jj + 1], ah, l2, l3);
                MMA16816(sacc[2 * jj],     al, h0, h1);
                MMA16816(sacc[2 * jj + 1], al, h2, h3);
            }
        }

        float mx0 = -3.0e38f, mx1 = -3.0e38f;
#pragma unroll
        for (int f = 0; f < 8; f++) {
            sacc[f][0] *= SCALE_F; sacc[f][1] *= SCALE_F;
            sacc[f][2] *= SCALE_F; sacc[f][3] *= SCALE_F;
            mx0 = fmaxf(mx0, fmaxf(sacc[f][0], sacc[f][1]));
            mx1 = fmaxf(mx1, fmaxf(sacc[f][2], sacc[f][3]));
        }
        mx0 = fmaxf(mx0, __shfl_xor_sync(0xffffffffu, mx0, 1));
        mx0 = fmaxf(mx0, __shfl_xor_sync(0xffffffffu, mx0, 2));
        mx1 = fmaxf(mx1, __shfl_xor_sync(0xffffffffu, mx1, 1));
        mx1 = fmaxf(mx1, __shfl_xor_sync(0xffffffffu, mx1, 2));

        float mnew0 = fmaxf(m_prev[0], mx0);
        float mnew1 = fmaxf(m_prev[1], mx1);
        float er0 = __expf(m_prev[0] - mnew0);
        float er1 = __expf(m_prev[1] - mnew1);
        m_prev[0] = mnew0; m_prev[1] = mnew1;

        float rsum0 = 0.f, rsum1 = 0.f;
#pragma unroll
        for (int f = 0; f < 8; f++) {
            sacc[f][0] = __expf(sacc[f][0] - mnew0);
            sacc[f][1] = __expf(sacc[f][1] - mnew0);
            sacc[f][2] = __expf(sacc[f][2] - mnew1);
            sacc[f][3] = __expf(sacc[f][3] - mnew1);
            rsum0 += sacc[f][0] + sacc[f][1];
            rsum1 += sacc[f][2] + sacc[f][3];
        }
        rsum0 += __shfl_xor_sync(0xffffffffu, rsum0, 1);
        rsum0 += __shfl_xor_sync(0xffffffffu, rsum0, 2);
        rsum1 += __shfl_xor_sync(0xffffffffu, rsum1, 1);
        rsum1 += __shfl_xor_sync(0xffffffffu, rsum1, 2);
        l_acc[0] = l_acc[0] * er0 + rsum0;
        l_acc[1] = l_acc[1] * er1 + rsum1;

#pragma unroll
        for (int f = 0; f < 16; f++) {
            oacc[f][0] *= er0; oacc[f][1] *= er0;
            oacc[f][2] *= er1; oacc[f][3] *= er1;
        }

        uint32_t aph[4][4], apl[4][4];
#pragma unroll
        for (int t = 0; t < 4; t++) {
#pragma unroll
            for (int half = 0; half < 2; half++) {
                const int f = 2 * t + half;
                uint32_t u0 = packbf(sacc[f][0], sacc[f][1]);
                uint32_t u1 = packbf(sacc[f][2], sacc[f][3]);
                aph[t][2 * half]     = u0;
                aph[t][2 * half + 1] = u1;
                apl[t][2 * half] =
                    packbf(sacc[f][0] - bflo_f(u0), sacc[f][1] - bfhi_f(u0));
                apl[t][2 * half + 1] =
                    packbf(sacc[f][2] - bflo_f(u1), sacc[f][3] - bfhi_f(u1));
            }
        }

#pragma unroll
        for (int t = 0; t < 4; t++) {
#pragma unroll
            for (int g = 0; g < 8; g++) {
                uint32_t h0, h1, h2, h3, l0, l1, l2, l3;
                LDSM_X4_T(h0, h1, h2, h3, sV  + vb + t * (16 * ASTR) + g * 32);
                LDSM_X4_T(l0, l1, l2, l3, sVl + vb + t * (16 * ASTR) + g * 32);
                MMA16816(oacc[2 * g],     aph[t], h0, h1);
                MMA16816(oacc[2 * g + 1], aph[t], h2, h3);
                MMA16816(oacc[2 * g],     aph[t], l0, l1);
                MMA16816(oacc[2 * g + 1], aph[t], l2, l3);
                MMA16816(oacc[2 * g],     apl[t], h0, h1);
                MMA16816(oacc[2 * g + 1], apl[t], h2, h3);
            }
        }
        __syncthreads();
    }

#pragma unroll
    for (int rs = 0; rs < 2; rs++) {
        const float inv = 1.0f / l_acc[rs];
        const int row = qrow0 + wm + (lane >> 2) + 8 * rs;
#pragma unroll
        for (int f = 0; f < 16; f++) {
            float v0 = oacc[f][2 * rs]     * inv;
            float v1 = oacc[f][2 * rs + 1] * inv;
            uint32_t hi = packbf(v0, v1);
            uint32_t lo = packbf(v0 - bflo_f(hi), v1 - bfhi_f(hi));
            const int col = hcol + f * 8 + 2 * (lane & 3);
            *(uint32_t*)(Oh + (size_t)row * DIMSZ + col) = hi;
            *(uint32_t*)(Ol + (size_t)row * DIMSZ + col) = lo;
        }
    }
}

// ---------------------------------------------------------------------------
extern "C" void kernel_launch(void* const* d_in, const int* in_sizes, int n_in,
                              void* d_out, int out_size)
{
    const float* x       = (const float*)d_in[0];
    const float* context = (const float*)d_in[1];
    const float* W_qkv   = (const float*)d_in[2];
    const float* b_qkv   = (const float*)d_in[3];
    const float* W_proj  = (const float*)d_in[4];
    const float* b_proj  = (const float*)d_in[5];
    float* out = (float*)d_out;

    __nv_bfloat16 *xh, *xl, *ch, *cl, *wqh, *wql, *wph, *wpl;
    __nv_bfloat16 *qh, *ql, *kvh, *kvl, *ath, *atl;
    cudaGetSymbolAddress((void**)&xh,  g_xh);  cudaGetSymbolAddress((void**)&xl,  g_xl);
    cudaGetSymbolAddress((void**)&ch,  g_ch);  cudaGetSymbolAddress((void**)&cl,  g_cl);
    cudaGetSymbolAddress((void**)&wqh, g_wqh); cudaGetSymbolAddress((void**)&wql, g_wql);
    cudaGetSymbolAddress((void**)&wph, g_wph); cudaGetSymbolAddress((void**)&wpl, g_wpl);
    cudaGetSymbolAddress((void**)&qh,  g_qh);  cudaGetSymbolAddress((void**)&ql,  g_ql);
    cudaGetSymbolAddress((void**)&kvh, g_kvh); cudaGetSymbolAddress((void**)&kvl, g_kvl);
    cudaGetSymbolAddress((void**)&ath, g_ath); cudaGetSymbolAddress((void**)&atl, g_atl);

    cudaFuncSetAttribute(gemm_mma, cudaFuncAttributeMaxDynamicSharedMemorySize, GEMM_SMEM);
    cudaFuncSetAttribute(attn_mma, cudaFuncAttributeMaxDynamicSharedMemorySize, ATT_SMEM);

    int nsm = 148;
    cudaDeviceGetAttribute(&nsm, cudaDevAttrMultiProcessorCount, 0);
    const int pgrid = 2 * nsm;

    const int n4 = MROWS * DIMSZ / 4;

    split_fp32<<<(n4 + 255) / 256, 256>>>(x, xh, xl, n4);
    split_fp32<<<(n4 + 255) / 256, 256>>>(context, ch, cl, n4);
    transpose_split<<<dim3(3 * DIMSZ / 32, DIMSZ / 32), 256>>>(W_qkv, wqh, wql, DIMSZ, 3 * DIMSZ);
    transpose_split<<<dim3(DIMSZ / 32, DIMSZ / 32), 256>>>(W_proj, wph, wpl, DIMSZ, DIMSZ);

    // qkv GEMM: tiles = 32 m x 48 n
    gemm_mma<<<pgrid, 256, GEMM_SMEM>>>(
        xh, xl, ch, cl, wqh, wql, b_qkv,
        nullptr, DIMSZ, nullptr, 2 * DIMSZ,
        qh, ql, kvh, kvl, DIMSZ, 1,
        MROWS / GBM, 3 * DIMSZ / GBN);

    attn_mma<<<dim3(LSEQ / 128, NHEADS, BSZ), 256, ATT_SMEM>>>(qh, ql, kvh, kvl, ath, atl);

    // proj GEMM: tiles = 32 m x 16 n
    gemm_mma<<<pgrid, 256, GEMM_SMEM>>>(
        ath, atl, ath, atl, wph, wpl, b_proj,
        out, DIMSZ, out, DIMSZ,
        nullptr, nullptr, nullptr, nullptr, 1 << 30, 0,
        MROWS / GBM, DIMSZ / GBN);
}